// round 9
// baseline (speedup 1.0000x reference)
#include <cuda_runtime.h>
#include <math.h>

#define H1 256
#define W1 256
#define HW1 65536
#define EPSF 1e-5f

typedef unsigned long long ull;
typedef unsigned int u32;

__device__ __forceinline__ ull pk2(float a, float b) {
    ull r; asm("mov.b64 %0,{%1,%2};" : "=l"(r) : "f"(a), "f"(b)); return r;
}
__device__ __forceinline__ ull dup2(float a) {
    ull r; asm("mov.b64 %0,{%1,%1};" : "=l"(r) : "f"(a)); return r;
}
__device__ __forceinline__ void fma2(ull& d, ull a, ull b) {
    asm("fma.rn.f32x2 %0,%1,%2,%0;" : "+l"(d) : "l"(a), "l"(b));
}
__device__ __forceinline__ ull sub2(ull a, ull b) {
    ull r; asm("sub.rn.f32x2 %0,%1,%2;" : "=l"(r) : "l"(a), "l"(b)); return r;
}
__device__ __forceinline__ float2 up2(ull u) {
    float2 r; asm("mov.b64 {%0,%1},%2;" : "=f"(r.x), "=f"(r.y) : "l"(u)); return r;
}
__device__ __forceinline__ u32 s2u(const void* p) {
    u32 a; asm("{.reg .u64 t; cvta.to.shared.u64 t, %1; cvt.u32.u64 %0, t;}" : "=r"(a) : "l"(p));
    return a;
}
__device__ __forceinline__ void cp16(u32 dst, const void* src) {
    asm volatile("cp.async.cg.shared.global [%0], [%1], 16;" :: "r"(dst), "l"(src));
}
__device__ __forceinline__ void cp_commit() {
    asm volatile("cp.async.commit_group;");
}
template<int N> __device__ __forceinline__ void cp_wait() {
    asm volatile("cp.async.wait_group %0;" :: "n"(N));
}

// ---------------- scratch ----------------
__device__ float g_h4[1024 + 2 * 64 * HW1 + 1024];        // pad + [b][c/4][p][4] + pad
__device__ float g_off[2 * 8 * HW1];
__device__ float g_outraw[2 * 16 * HW1];
__device__ __align__(16) ull g_woff2[64 * 9 * 6];         // [c][tap(9)][vch-pair(6)]
__device__ float g_osum[12], g_osq[12];
__device__ float g_ssum[8],  g_ssq[8];

// ---------------- prep ----------------
__global__ void prep_kernel(const float* __restrict__ wx, const float* __restrict__ wy) {
    int idx = blockIdx.x * 256 + threadIdx.x;
    if (idx < 12) { g_osum[idx] = 0.f; g_osq[idx] = 0.f; }
    if (idx < 8)  { g_ssum[idx] = 0.f; g_ssq[idx] = 0.f; }
    if (idx < 1024) {
        g_h4[idx] = 0.f;
        g_h4[1024 + 2 * 64 * HW1 + idx] = 0.f;
    }
    if (idx < 3456) {
        int c = idx / 54, rem = idx - c * 54;
        int t = rem / 6, j = rem - t * 6;
        int v0 = 2 * j, v1 = 2 * j + 1;
        float a = (v0 < 6) ? wx[v0 * 576 + c * 9 + t] : wy[(v0 - 2) * 576 + c * 9 + t];
        float b = (v1 < 6) ? wx[v1 * 576 + c * 9 + t] : wy[(v1 - 2) * 576 + c * 9 + t];
        g_woff2[idx] = pk2(a, b);
    }
}

// ---------------- conv1 3x3 s2 pad1 (3->64) + BN + ReLU; vec4 layout only ----------------
__global__ void __launch_bounds__(256) conv1_kernel(
        const float* __restrict__ x, const float* __restrict__ w,
        const float* __restrict__ g, const float* __restrict__ bb,
        const float* __restrict__ m, const float* __restrict__ v) {
    __shared__ __align__(16) ull swp[864];
    __shared__ float ssc[64], ssh[64];
    int tid = threadIdx.x;
    for (int i = tid; i < 864; i += 256) {
        int t = i >> 5, op = i & 31;
        swp[i] = pk2(w[(2 * op) * 27 + t], w[(2 * op + 1) * 27 + t]);
    }
    if (tid < 64) {
        float sc = g[tid] * rsqrtf(v[tid] + EPSF);
        ssc[tid] = sc; ssh[tid] = bb[tid] - m[tid] * sc;
    }
    __syncthreads();

    int idx = blockIdx.x * 256 + tid;
    int b = idx >> 16, p = idx & 65535;
    int oy = p >> 8, ox = p & 255;
    const float* xb = x + (size_t)b * 3 * 512 * 512;

    ull pd[27];
    #pragma unroll
    for (int ic = 0; ic < 3; ic++)
        #pragma unroll
        for (int dy = 0; dy < 3; dy++) {
            int iy = 2 * oy - 1 + dy;
            #pragma unroll
            for (int dx = 0; dx < 3; dx++) {
                int ix = 2 * ox - 1 + dx;
                float val = 0.f;
                if (iy >= 0 && ix >= 0) val = xb[(ic * 512 + iy) * 512 + ix];
                pd[ic * 9 + dy * 3 + dx] = dup2(val);
            }
        }

    float4* hb4 = (float4*)g_h4 + 64 + (size_t)b * 16 * HW1 + p;
    #pragma unroll 1
    for (int half = 0; half < 2; half++) {
        ull acc[16];
        #pragma unroll
        for (int j = 0; j < 16; j++) acc[j] = 0ull;
        #pragma unroll
        for (int t = 0; t < 27; t++)
            #pragma unroll
            for (int j = 0; j < 16; j++)
                fma2(acc[j], pd[t], swp[t * 32 + half * 16 + j]);
        #pragma unroll
        for (int mm = 0; mm < 8; mm++) {
            int oc = (half * 8 + mm) * 4;
            float2 v0 = up2(acc[2 * mm]);
            float2 v1 = up2(acc[2 * mm + 1]);
            float r0 = fmaxf(fmaf(v0.x, ssc[oc],     ssh[oc]),     0.f);
            float r1 = fmaxf(fmaf(v0.y, ssc[oc + 1], ssh[oc + 1]), 0.f);
            float r2 = fmaxf(fmaf(v1.x, ssc[oc + 2], ssh[oc + 2]), 0.f);
            float r3 = fmaxf(fmaf(v1.y, ssc[oc + 3], ssh[oc + 3]), 0.f);
            hb4[(size_t)(half * 8 + mm) * HW1] = make_float4(r0, r1, r2, r3);
        }
    }
}

// ---------------- offset convs: direct LDG.128 gather, barrier-free, vch-pair packed ----------------
__global__ void __launch_bounds__(256) offconv_kernel(
        const float* __restrict__ bxp, const float* __restrict__ byp) {
    __shared__ __align__(16) ulonglong2 swq[1728];   // [c][tap][3 x vch-pair-pair]
    int tid = threadIdx.x;
    const ulonglong2* wg = (const ulonglong2*)g_woff2;
    for (int i = tid; i < 1728; i += 256) swq[i] = wg[i];
    __syncthreads();

    int idx = blockIdx.x * 256 + tid;
    int b = idx >> 16, p = idx & 65535;
    int oy = p >> 8, ox = p & 255;

    int off[9];
    bool okt[9];
    #pragma unroll
    for (int dy = 0; dy < 3; dy++)
        #pragma unroll
        for (int dx = 0; dx < 3; dx++) {
            int iy = oy - 1 + dy, ix = ox - 1 + dx;
            okt[dy * 3 + dx] = (iy >= 0) && (iy < H1) && (ix >= 0) && (ix < W1);
            off[dy * 3 + dx] = iy * W1 + ix;
        }

    ull acc[6];
    #pragma unroll
    for (int j = 0; j < 6; j++) {
        int v0 = 2 * j, v1 = 2 * j + 1;
        float a = (v0 < 6) ? bxp[v0] : byp[v0 - 2];
        float c = (v1 < 6) ? bxp[v1] : byp[v1 - 2];
        acc[j] = pk2(a, c);
    }

    const float4* g4 = (const float4*)g_h4 + 64 + (size_t)b * 16 * HW1;
    #pragma unroll 1
    for (int cg = 0; cg < 16; cg++) {
        const float4* gp = g4 + (size_t)cg * HW1;
        float4 A[9];
        #pragma unroll
        for (int t = 0; t < 9; t++)
            A[t] = okt[t] ? __ldg(gp + off[t]) : make_float4(0.f, 0.f, 0.f, 0.f);

        #pragma unroll
        for (int ch = 0; ch < 4; ch++) {
            const ulonglong2* wc = swq + (cg * 4 + ch) * 27;
            #pragma unroll
            for (int t = 0; t < 9; t++) {
                float av = (ch == 0) ? A[t].x : (ch == 1) ? A[t].y : (ch == 2) ? A[t].z : A[t].w;
                ull v = dup2(av);
                ulonglong2 w01 = wc[t * 3], w23 = wc[t * 3 + 1], w45 = wc[t * 3 + 2];
                fma2(acc[0], v, w01.x); fma2(acc[1], v, w01.y);
                fma2(acc[2], v, w23.x); fma2(acc[3], v, w23.y);
                fma2(acc[4], v, w45.x); fma2(acc[5], v, w45.y);
            }
        }
    }

    // stores: vch {0,1,3,4, 7,8,10,11} -> planes 0..7
    float2 a0 = up2(acc[0]), a1 = up2(acc[1]), a2 = up2(acc[2]);
    float2 a3 = up2(acc[3]), a4 = up2(acc[4]), a5 = up2(acc[5]);
    float* ob = g_off + (size_t)b * 8 * HW1 + p;
    ob[0 * (size_t)HW1] = a0.x;  ob[1 * (size_t)HW1] = a0.y;
    ob[2 * (size_t)HW1] = a1.y;  ob[3 * (size_t)HW1] = a2.x;
    ob[4 * (size_t)HW1] = a3.y;  ob[5 * (size_t)HW1] = a4.x;
    ob[6 * (size_t)HW1] = a5.x;  ob[7 * (size_t)HW1] = a5.y;

    // stats: 6 groups = the 6 vch pairs
    int lane = tid & 31;
    #pragma unroll
    for (int gi = 0; gi < 6; gi++) {
        float2 a = up2(acc[gi]);
        float s = a.x + a.y;
        float q = a.x * a.x + a.y * a.y;
        #pragma unroll
        for (int o = 16; o > 0; o >>= 1) {
            s += __shfl_down_sync(0xffffffffu, s, o);
            q += __shfl_down_sync(0xffffffffu, q, o);
        }
        if (lane == 0) {
            atomicAdd(&g_osum[b * 6 + gi], s);
            atomicAdd(&g_osq[b * 6 + gi], q);
        }
    }
}

// ---------------- smem-tiled sampler (round 8, unchanged) ----------------
#define SROWS 21
#define SCOLS 40
#define SCELLS (SROWS * SCOLS)
#define STILEB (SCELLS * 16)
__global__ void __launch_bounds__(256) sample_kernel(
        const float* __restrict__ dwx, const float* __restrict__ dbx,
        const float* __restrict__ dwy, const float* __restrict__ dby,
        const float* __restrict__ gxg, const float* __restrict__ gxb,
        const float* __restrict__ gyg, const float* __restrict__ gyb) {
    int bz = blockIdx.z;
    int b = bz >> 1, morph = bz & 1;
    const float* dw = morph ? dwy : dwx;
    const float* db = morph ? dby : dbx;

    __shared__ __align__(16) float4 tile[2][SCELLS];
    __shared__ __align__(16) ull sw2[1280];
    __shared__ float sA[4], sB[4];
    int tid = threadIdx.x, tx = tid & 31, ty = tid >> 5;
    int ox0 = blockIdx.x * 32, oy0 = blockIdx.y * 16;

    for (int i = tid; i < 1280; i += 256) {
        int cg = i / 80, r = i - cg * 80;
        int k = r >> 4, r2 = r & 15;
        int cp = r2 >> 3, oc = r2 & 7;
        int c0 = cg * 4 + cp * 2;
        sw2[i] = pk2(dw[oc * 320 + c0 * 5 + k], dw[oc * 320 + (c0 + 1) * 5 + k]);
    }
    if (tid < 4) {
        int gi, ci; float gamma, beta;
        if (morph == 0) {
            const int gtab[4] = {0, 0, 1, 2}; const int ctab[4] = {0, 1, 3, 4};
            gi = b * 6 + gtab[tid]; ci = ctab[tid];
            gamma = gxg[ci]; beta = gxb[ci];
        } else {
            const int gtab[4] = {3, 4, 5, 5}; const int ctab[4] = {5, 6, 8, 9};
            gi = b * 6 + gtab[tid]; ci = ctab[tid];
            gamma = gyg[ci]; beta = gyb[ci];
        }
        float mean = g_osum[gi] * (1.f / 131072.f);
        float var  = g_osq[gi]  * (1.f / 131072.f) - mean * mean;
        float rs = rsqrtf(var + EPSF) * gamma;
        sA[tid] = rs; sB[tid] = beta - mean * rs;
    }

    int soff[4]; u32 sdst[4];
    #pragma unroll
    for (int s = 0; s < 4; s++) {
        int i = tid + s * 256;
        if (i < SCELLS) {
            int r = i / SCOLS, c4 = i - r * SCOLS;
            int gy = min(max(oy0 - 2 + r, 0), 255);
            soff[s] = gy * 256 + ox0 - 4 + c4;
            sdst[s] = s2u(&tile[0][0]) + i * 16;
        } else {
            soff[s] = 1 << 30;
        }
    }
    const float4* g4 = (const float4*)g_h4 + 64 + (size_t)b * 16 * HW1;
    int step = morph ? 1 : SCOLS;

    __syncthreads();

    int o0[2][5];
    float wt[2][5];
    #pragma unroll
    for (int j = 0; j < 2; j++) {
        int yy = oy0 + ty + 8 * j;
        int ww = ox0 + tx;
        int p = yy * W1 + ww;
        const float* ob = g_off + ((size_t)b * 8 + morph * 4) * HW1 + p;
        float t0 = tanhf(fmaf(ob[0 * (size_t)HW1], sA[0], sB[0]));
        float t1 = tanhf(fmaf(ob[1 * (size_t)HW1], sA[1], sB[1]));
        float t2 = tanhf(fmaf(ob[2 * (size_t)HW1], sA[2], sB[2]));
        float t3 = tanhf(fmaf(ob[3 * (size_t)HW1], sA[3], sB[3]));
        float cum[5] = {t0 + t1, t1, 0.f, t2, t2 + t3};
        #pragma unroll
        for (int k = 0; k < 5; k++) {
            if (morph == 0) {
                float y = fminf(fmaxf((float)yy + cum[k], 0.f), 255.f);
                float y0 = floorf(y);
                wt[j][k] = y - y0;
                int xi = min(max(ox0 + tx + k - 2, 0), 255);
                o0[j][k] = ((int)y0 - oy0 + 2) * SCOLS + (xi - ox0 + 4);
            } else {
                float xx = fminf(fmaxf((float)(ox0 + tx) + cum[k], 0.f), 255.f);
                float x0 = floorf(xx);
                wt[j][k] = xx - x0;
                int yi = min(max(yy + k - 2, 0), 255);
                o0[j][k] = (yi - oy0 + 2) * SCOLS + ((int)x0 - ox0 + 4);
            }
        }
    }

    ull acc[2][8];
    #pragma unroll
    for (int j = 0; j < 2; j++)
        #pragma unroll
        for (int oc = 0; oc < 8; oc++) acc[j][oc] = 0ull;

    {
        #pragma unroll
        for (int s = 0; s < 4; s++)
            if (soff[s] < (1 << 29)) cp16(sdst[s], g4 + soff[s]);
        cp_commit();
    }

    #pragma unroll 1
    for (int cg = 0; cg < 16; cg++) {
        int buf = cg & 1;
        if (cg + 1 < 16) {
            u32 boff = (buf ^ 1) * STILEB;
            const float4* gsrc = g4 + (size_t)(cg + 1) * HW1;
            #pragma unroll
            for (int s = 0; s < 4; s++)
                if (soff[s] < (1 << 29)) cp16(sdst[s] + boff, gsrc + soff[s]);
            cp_commit();
            cp_wait<1>();
        } else {
            cp_wait<0>();
        }
        __syncthreads();

        const float4* tp = tile[buf];
        const ulonglong2* wq = (const ulonglong2*)sw2 + cg * 40;
        #pragma unroll
        for (int k = 0; k < 5; k++) {
            ull v01[2], v23[2];
            #pragma unroll
            for (int j = 0; j < 2; j++) {
                float4 A = tp[o0[j][k]];
                if (k == 2) {
                    v01[j] = pk2(A.x, A.y);
                    v23[j] = pk2(A.z, A.w);
                } else {
                    float4 Bv = tp[o0[j][k] + step];
                    ull w2d = dup2(wt[j][k]);
                    ull a01 = pk2(A.x, A.y), a23 = pk2(A.z, A.w);
                    ull d01 = sub2(pk2(Bv.x, Bv.y), a01);
                    ull d23 = sub2(pk2(Bv.z, Bv.w), a23);
                    fma2(a01, w2d, d01);
                    fma2(a23, w2d, d23);
                    v01[j] = a01; v23[j] = a23;
                }
            }
            #pragma unroll
            for (int q = 0; q < 4; q++) {
                ulonglong2 wA = wq[k * 8 + q];
                ulonglong2 wB = wq[k * 8 + 4 + q];
                #pragma unroll
                for (int j = 0; j < 2; j++) {
                    fma2(acc[j][2 * q],     v01[j], wA.x);
                    fma2(acc[j][2 * q + 1], v01[j], wA.y);
                    fma2(acc[j][2 * q],     v23[j], wB.x);
                    fma2(acc[j][2 * q + 1], v23[j], wB.y);
                }
            }
        }
        __syncthreads();
    }

    float* op = g_outraw + ((size_t)b * 16 + morph * 8) * HW1;
    float rr[2][8];
    #pragma unroll
    for (int j = 0; j < 2; j++) {
        int p = (oy0 + ty + 8 * j) * W1 + ox0 + tx;
        #pragma unroll
        for (int oc = 0; oc < 8; oc++) {
            float2 t = up2(acc[j][oc]);
            float r = t.x + t.y + __ldg(db + oc);
            rr[j][oc] = r;
            op[(size_t)oc * HW1 + p] = r;
        }
    }

    int lane = tid & 31;
    #pragma unroll
    for (int gi = 0; gi < 2; gi++) {
        float s = 0.f, q = 0.f;
        #pragma unroll
        for (int j = 0; j < 2; j++)
            #pragma unroll
            for (int oc = 4 * gi; oc < 4 * gi + 4; oc++) {
                s += rr[j][oc];
                q = fmaf(rr[j][oc], rr[j][oc], q);
            }
        #pragma unroll
        for (int o = 16; o > 0; o >>= 1) {
            s += __shfl_down_sync(0xffffffffu, s, o);
            q += __shfl_down_sync(0xffffffffu, q, o);
        }
        if (lane == 0) {
            atomicAdd(&g_ssum[b * 4 + morph * 2 + gi], s);
            atomicAdd(&g_ssq[b * 4 + morph * 2 + gi], q);
        }
    }
}

// ---------------- GN+ReLU + concat + 1x1 conv (16->64) + BN + ReLU ----------------
__global__ void __launch_bounds__(256) final_kernel(
        const float* __restrict__ gx_g, const float* __restrict__ gx_b,
        const float* __restrict__ gy_g, const float* __restrict__ gy_b,
        const float* __restrict__ w2,
        const float* __restrict__ bn2g, const float* __restrict__ bn2b,
        const float* __restrict__ bn2m, const float* __restrict__ bn2v,
        float* __restrict__ out) {
    __shared__ __align__(16) ull swt[16 * 32];
    __shared__ ull scp[32], shp[32];
    __shared__ float gnA[16], gnB[16];
    int tid = threadIdx.x;
    int idx = blockIdx.x * 256 + tid;
    int b = idx >> 16, p = idx & 65535;

    for (int i = tid; i < 512; i += 256) {
        int ch = i >> 5, op = i & 31;
        swt[i] = pk2(w2[(2 * op) * 16 + ch], w2[(2 * op + 1) * 16 + ch]);
    }
    if (tid < 32) {
        int oc0 = 2 * tid, oc1 = 2 * tid + 1;
        float sc0 = bn2g[oc0] * rsqrtf(bn2v[oc0] + EPSF);
        float sc1 = bn2g[oc1] * rsqrtf(bn2v[oc1] + EPSF);
        scp[tid] = pk2(sc0, sc1);
        shp[tid] = pk2(bn2b[oc0] - bn2m[oc0] * sc0, bn2b[oc1] - bn2m[oc1] * sc1);
    }
    if (tid < 16) {
        int ch = tid;
        int gi = b * 4 + ch / 4;
        float mean = g_ssum[gi] * (1.f / 262144.f);
        float var  = g_ssq[gi]  * (1.f / 262144.f) - mean * mean;
        float rs = rsqrtf(var + EPSF);
        float gamma = (ch < 8) ? gx_g[ch] : gy_g[ch - 8];
        float beta  = (ch < 8) ? gx_b[ch] : gy_b[ch - 8];
        gnA[ch] = rs * gamma; gnB[ch] = beta - mean * rs * gamma;
    }
    __syncthreads();

    ull catd[16];
    #pragma unroll
    for (int ch = 0; ch < 16; ch++) {
        float val = g_outraw[((size_t)b * 16 + ch) * HW1 + p];
        val = fmaxf(fmaf(val, gnA[ch], gnB[ch]), 0.f);
        catd[ch] = dup2(val);
    }

    ull acc[32];
    #pragma unroll
    for (int i = 0; i < 32; i++) acc[i] = 0ull;
    #pragma unroll
    for (int ch = 0; ch < 16; ch++) {
        const ulonglong2* wrow = (const ulonglong2*)(swt + ch * 32);
        #pragma unroll
        for (int op2 = 0; op2 < 16; op2++) {
            ulonglong2 ww = wrow[op2];
            fma2(acc[2 * op2], catd[ch], ww.x);
            fma2(acc[2 * op2 + 1], catd[ch], ww.y);
        }
    }

    float* obp = out + (size_t)b * 64 * HW1 + p;
    #pragma unroll
    for (int op = 0; op < 32; op++) {
        ull tmp = shp[op];
        fma2(tmp, acc[op], scp[op]);
        float2 vv = up2(tmp);
        obp[(size_t)(2 * op) * HW1]     = fmaxf(vv.x, 0.f);
        obp[(size_t)(2 * op + 1) * HW1] = fmaxf(vv.y, 0.f);
    }
}

// ---------------- launch ----------------
extern "C" void kernel_launch(void* const* d_in, const int* in_sizes, int n_in,
                              void* d_out, int out_size) {
    const float* x        = (const float*)d_in[0];
    const float* conv1_w  = (const float*)d_in[1];
    const float* bn1_g    = (const float*)d_in[2];
    const float* bn1_b    = (const float*)d_in[3];
    const float* bn1_m    = (const float*)d_in[4];
    const float* bn1_v    = (const float*)d_in[5];
    const float* offx_w   = (const float*)d_in[6];
    const float* offx_b   = (const float*)d_in[7];
    const float* gnoffx_g = (const float*)d_in[8];
    const float* gnoffx_b = (const float*)d_in[9];
    const float* dscx_w   = (const float*)d_in[10];
    const float* dscx_b   = (const float*)d_in[11];
    const float* gnx_g    = (const float*)d_in[12];
    const float* gnx_b    = (const float*)d_in[13];
    const float* offy_w   = (const float*)d_in[14];
    const float* offy_b   = (const float*)d_in[15];
    const float* gnoffy_g = (const float*)d_in[16];
    const float* gnoffy_b = (const float*)d_in[17];
    const float* dscy_w   = (const float*)d_in[18];
    const float* dscy_b   = (const float*)d_in[19];
    const float* gny_g    = (const float*)d_in[20];
    const float* gny_b    = (const float*)d_in[21];
    const float* conv2_w  = (const float*)d_in[22];
    const float* bn2_g    = (const float*)d_in[23];
    const float* bn2_b    = (const float*)d_in[24];
    const float* bn2_m    = (const float*)d_in[25];
    const float* bn2_v    = (const float*)d_in[26];
    float* out = (float*)d_out;

    prep_kernel<<<14, 256>>>(offx_w, offy_w);
    conv1_kernel<<<512, 256>>>(x, conv1_w, bn1_g, bn1_b, bn1_m, bn1_v);
    offconv_kernel<<<512, 256>>>(offx_b, offy_b);
    sample_kernel<<<dim3(8, 16, 4), 256>>>(dscx_w, dscx_b, dscy_w, dscy_b,
                                           gnoffx_g, gnoffx_b, gnoffy_g, gnoffy_b);
    final_kernel<<<512, 256>>>(gnx_g, gnx_b, gny_g, gny_b, conv2_w,
                               bn2_g, bn2_b, bn2_m, bn2_v, out);
}